// round 2
// baseline (speedup 1.0000x reference)
#include <cuda_runtime.h>
#include <math.h>
#include <stdint.h>

#define HFD 128
#define WFD 128
#define DFD 512
#define NA  65536
#define MAXDET 512
#define HIDDEN 1024
#define PD 4608          // 3*3*512
#define NBINS 2048
#define MAXCAND 4096

// ---------------- scratch (device globals; no allocation allowed) ----------
__device__ float    g_scores[NA];
__device__ float4   g_boxes[NA];
__device__ unsigned g_hist[NBINS];
__device__ unsigned g_candCount;
__device__ unsigned g_cutoff;
__device__ unsigned long long g_cand[MAXCAND];
__device__ float    g_topscore[MAXDET];
__device__ int      g_valid[MAXDET];
__device__ float4   g_sel[MAXDET];
__device__ unsigned g_adj[MAXDET * 16];
__device__ unsigned char g_keep[MAXDET];
__device__ float    g_pooled[MAXDET * PD];
__device__ float    g_h1[MAXDET * HIDDEN];
__device__ float    g_h2[MAXDET * HIDDEN];

// ---------------- kernels ---------------------------------------------------

__global__ void k_zero() {
    int t = blockIdx.x * blockDim.x + threadIdx.x;
    if (t < NBINS) g_hist[t] = 0u;
    if (t == 0)    g_candCount = 0u;
}

// scores, boxes, histogram of score bits (scores in (0.5, 1.0])
__global__ void k_scorebox(const float* __restrict__ obj,
                           const float* __restrict__ reg,
                           const float* __restrict__ anchors) {
    __shared__ unsigned sh[NBINS];
    for (int i = threadIdx.x; i < NBINS; i += blockDim.x) sh[i] = 0u;
    __syncthreads();

    int a  = blockIdx.x * blockDim.x + threadIdx.x;   // 0..65535
    int kk = a & 3;
    int jj = (a >> 2) & 127;
    int ii = a >> 9;
    int pix = ii * WFD + jj;

    float o0 = obj[pix * 8 + 2 * kk];
    float o1 = obj[pix * 8 + 2 * kk + 1];
    float mx = fmaxf(o0, o1);
    float e0 = expf(o0 - mx), e1 = expf(o1 - mx);
    float s  = e1 / (e0 + e1);
    g_scores[a] = s;

    const float* r = reg + pix * 16 + 4 * kk;
    float r0 = r[0], r1 = r[1], r2 = r[2], r3 = r[3];
    const float* an = anchors + a * 4;
    float ax = an[0], ay = an[1], aw = an[2], ah = an[3];
    float acx = ax + aw * 0.5f;
    float acy = ay + ah * 0.5f;
    float cx = acx + r0 * aw;
    float cy = acy + r1 * ah;
    float w  = aw * expf(r2);
    float h  = ah * expf(r3);
    g_boxes[a] = make_float4(cx - w * 0.5f, cy - h * 0.5f, w, h);

    if (s > 0.5f) {
        unsigned bits = __float_as_uint(s);
        unsigned bin  = (bits - 0x3F000001u) >> 12;   // 0..2047, monotone
        atomicAdd(&sh[bin], 1u);
    }
    __syncthreads();
    for (int i = threadIdx.x; i < NBINS; i += blockDim.x)
        if (sh[i]) atomicAdd(&g_hist[i], sh[i]);
}

__global__ void k_cutoff() {
    unsigned cum = 0;
    int b;
    for (b = NBINS - 1; b >= 0; b--) {
        cum += g_hist[b];
        if (cum >= MAXDET) break;
    }
    if (b < 0) b = 0;
    g_cutoff = (unsigned)b;
}

__global__ void k_compact() {
    int a = blockIdx.x * blockDim.x + threadIdx.x;
    float s = g_scores[a];
    if (s > 0.5f) {
        unsigned bits = __float_as_uint(s);
        unsigned bin  = (bits - 0x3F000001u) >> 12;
        if (bin >= g_cutoff) {
            unsigned pos = atomicAdd(&g_candCount, 1u);
            if (pos < MAXCAND)
                g_cand[pos] = ((unsigned long long)bits << 32)
                            | (unsigned long long)(0xFFFFFFFFu - (unsigned)a);
        }
    }
}

// bitonic sort candidates descending; emit top-512 (score, idx, sel box, valid)
__global__ void k_sortselect() {
    __shared__ unsigned long long s[MAXCAND];   // 32 KB
    unsigned n = g_candCount;
    if (n > MAXCAND) n = MAXCAND;
    for (int i = threadIdx.x; i < MAXCAND; i += blockDim.x)
        s[i] = (i < (int)n) ? g_cand[i] : 0ull;
    __syncthreads();

    for (int k = 2; k <= MAXCAND; k <<= 1) {
        for (int j = k >> 1; j > 0; j >>= 1) {
            for (int i = threadIdx.x; i < MAXCAND; i += blockDim.x) {
                int ixj = i ^ j;
                if (ixj > i) {
                    unsigned long long va = s[i], vb = s[ixj];
                    bool swp = ((i & k) == 0) ? (va < vb) : (va > vb);
                    if (swp) { s[i] = vb; s[ixj] = va; }
                }
            }
            __syncthreads();
        }
    }

    for (int i = threadIdx.x; i < MAXDET; i += blockDim.x) {
        unsigned long long key = s[i];
        if (key != 0ull) {
            unsigned bits = (unsigned)(key >> 32);
            unsigned idx  = 0xFFFFFFFFu - (unsigned)(key & 0xFFFFFFFFull);
            g_topscore[i] = __uint_as_float(bits);
            g_valid[i]    = 1;
            g_sel[i]      = g_boxes[idx];
        } else {
            g_topscore[i] = 0.0f;
            g_valid[i]    = 0;
            g_sel[i]      = make_float4(0.f, 0.f, 0.f, 0.f);
        }
    }
}

// adjacency bitmask: word w of row i holds bits for j in [32w, 32w+32), j<i, iou>0.3
__global__ void k_adj() {
    int t = blockIdx.x * blockDim.x + threadIdx.x;   // 0..8191
    int i = t >> 4;
    int w = t & 15;
    float4 bi = g_sel[i];
    float x1i = bi.x, y1i = bi.y;
    float x2i = bi.x + bi.z, y2i = bi.y + bi.w;
    float areai = bi.z * bi.w;
    unsigned mask = 0u;
    int j0 = w * 32;
    #pragma unroll 4
    for (int jj = 0; jj < 32; jj++) {
        int j = j0 + jj;
        if (j >= i) break;
        float4 bj = g_sel[j];
        float x2j = bj.x + bj.z, y2j = bj.y + bj.w;
        float ix = fminf(x2i, x2j) - fmaxf(x1i, bj.x);
        ix = fmaxf(0.0f, ix);
        float iy = fminf(y2i, y2j) - fmaxf(y1i, bj.y);
        iy = fmaxf(0.0f, iy);
        float inter = ix * iy;
        float areaj = bj.z * bj.w;
        float iou = inter / (areai + areaj - inter + 1e-8f);
        if (iou > 0.3f) mask |= (1u << jj);
    }
    g_adj[t] = mask;
}

// sequential NMS scan over 512-bit keep mask (warp 0; adjacency in smem)
__global__ void k_nms() {
    __shared__ unsigned s_adj[MAXDET * 16];
    __shared__ int s_valid[MAXDET];
    __shared__ unsigned s_kw[16];
    int t = threadIdx.x;
    for (int i = t; i < MAXDET * 16; i += blockDim.x) s_adj[i] = g_adj[i];
    if (t < MAXDET) s_valid[t] = g_valid[t];
    __syncthreads();

    if (t < 32) {
        unsigned kw = 0u;
        for (int i = 0; i < MAXDET; i++) {
            unsigned w = (t < 16) ? s_adj[i * 16 + t] : 0u;
            bool sup = __any_sync(0xffffffffu, (w & kw) != 0u);
            bool k = (s_valid[i] != 0) && !sup;
            if (t == (i >> 5)) kw |= ((unsigned)k) << (i & 31);
        }
        if (t < 16) s_kw[t] = kw;
    }
    __syncthreads();
    if (t < MAXDET) g_keep[t] = (unsigned char)((s_kw[t >> 5] >> (t & 31)) & 1u);
}

// ROIAlign: block = (tile 0..8, box 0..511); threads over channels
__global__ void k_roialign(const float* __restrict__ feat) {
    int tile = blockIdx.x;
    int m    = blockIdx.y;
    int ty = tile / 3, tx = tile % 3;
    float4 b = g_sel[m];

    int x0[2], x1[2], y0[2], y1[2];
    float wx[2], wy[2];
    #pragma unroll
    for (int p = 0; p < 2; p++) {
        {
            int sx = tx * 2 + p;
            float tt = ((float)sx + 0.5f) / 6.0f;
            float c = (b.x + tt * b.z) / 16.0f - 0.5f;
            c = fminf(fmaxf(c, 0.0f), 127.0f);
            int c0 = (int)floorf(c);
            x0[p] = c0;
            x1[p] = min(c0 + 1, 127);
            wx[p] = c - (float)c0;
        }
        {
            int sy = ty * 2 + p;
            float tt = ((float)sy + 0.5f) / 6.0f;
            float c = (b.y + tt * b.w) / 16.0f - 0.5f;
            c = fminf(fmaxf(c, 0.0f), 127.0f);
            int c0 = (int)floorf(c);
            y0[p] = c0;
            y1[p] = min(c0 + 1, 127);
            wy[p] = c - (float)c0;
        }
    }

    for (int c = threadIdx.x; c < DFD; c += blockDim.x) {
        float mv = -INFINITY;
        #pragma unroll
        for (int py = 0; py < 2; py++) {
            float w0y = 1.0f - wy[py], w1y = wy[py];
            #pragma unroll
            for (int px = 0; px < 2; px++) {
                float w0x = 1.0f - wx[px], w1x = wx[px];
                float f00 = feat[(y0[py] * WFD + x0[px]) * DFD + c];
                float f01 = feat[(y0[py] * WFD + x1[px]) * DFD + c];
                float f10 = feat[(y1[py] * WFD + x0[px]) * DFD + c];
                float f11 = feat[(y1[py] * WFD + x1[px]) * DFD + c];
                // match reference op order: (f*wy)*wx, left-assoc sum
                float v = ((f00 * w0y) * w0x) + ((f01 * w0y) * w1x)
                        + ((f10 * w1y) * w0x) + ((f11 * w1y) * w1x);
                mv = fmaxf(mv, v);
            }
        }
        g_pooled[(m * 9 + tile) * DFD + c] = mv;
    }
}

// fp32 SIMT GEMM: C = relu?(A[MxK] * B[KxN] + bias), 64x64x16 tiles, 256 thr
__global__ __launch_bounds__(256) void k_gemm(const float* __restrict__ A,
                                              const float* __restrict__ B,
                                              const float* __restrict__ bias,
                                              float* __restrict__ C,
                                              int M, int N, int Ksz, int relu) {
    __shared__ float As[16 * 64];
    __shared__ float Bs[16 * 64];
    int tid = threadIdx.x;
    int rowBase = blockIdx.y * 64;
    int colBase = blockIdx.x * 64;
    int am = tid >> 2, ak = (tid & 3) << 2;
    int bk = tid >> 4, bn = (tid & 15) << 2;
    int ty = tid >> 4, tx = tid & 15;

    float c00=0,c01=0,c02=0,c03=0, c10=0,c11=0,c12=0,c13=0;
    float c20=0,c21=0,c22=0,c23=0, c30=0,c31=0,c32=0,c33=0;

    for (int k0 = 0; k0 < Ksz; k0 += 16) {
        float4 av = *(const float4*)(A + (size_t)(rowBase + am) * Ksz + k0 + ak);
        As[(ak + 0) * 64 + am] = av.x;
        As[(ak + 1) * 64 + am] = av.y;
        As[(ak + 2) * 64 + am] = av.z;
        As[(ak + 3) * 64 + am] = av.w;
        float4 bv = *(const float4*)(B + (size_t)(k0 + bk) * N + colBase + bn);
        *(float4*)&Bs[bk * 64 + bn] = bv;
        __syncthreads();
        #pragma unroll
        for (int k = 0; k < 16; k++) {
            float4 a  = *(float4*)&As[k * 64 + ty * 4];
            float4 bq = *(float4*)&Bs[k * 64 + tx * 4];
            c00 += a.x * bq.x; c01 += a.x * bq.y; c02 += a.x * bq.z; c03 += a.x * bq.w;
            c10 += a.y * bq.x; c11 += a.y * bq.y; c12 += a.y * bq.z; c13 += a.y * bq.w;
            c20 += a.z * bq.x; c21 += a.z * bq.y; c22 += a.z * bq.z; c23 += a.z * bq.w;
            c30 += a.w * bq.x; c31 += a.w * bq.y; c32 += a.w * bq.z; c33 += a.w * bq.w;
        }
        __syncthreads();
    }

    float4 bb = *(const float4*)(bias + colBase + tx * 4);
    float acc[4][4] = {{c00,c01,c02,c03},{c10,c11,c12,c13},
                       {c20,c21,c22,c23},{c30,c31,c32,c33}};
    #pragma unroll
    for (int i = 0; i < 4; i++) {
        float4 v = make_float4(acc[i][0] + bb.x, acc[i][1] + bb.y,
                               acc[i][2] + bb.z, acc[i][3] + bb.w);
        if (relu) {
            v.x = fmaxf(v.x, 0.f); v.y = fmaxf(v.y, 0.f);
            v.z = fmaxf(v.z, 0.f); v.w = fmaxf(v.w, 0.f);
        }
        int row = rowBase + ty * 4 + i;
        *(float4*)(C + (size_t)row * N + colBase + tx * 4) = v;
    }
}

// GEMM3 (512x4x1024) + unparameterize + keep/valid epilogue
__global__ void k_final(const float* __restrict__ W3,
                        const float* __restrict__ b3,
                        float* __restrict__ out) {
    int m = blockIdx.x;
    __shared__ float red[128 * 4];
    float a0 = 0.f, a1 = 0.f, a2 = 0.f, a3 = 0.f;
    const float* h = g_h2 + m * HIDDEN;
    for (int k = threadIdx.x; k < HIDDEN; k += 128) {
        float hv = h[k];
        const float* w = W3 + k * 4;
        a0 += hv * w[0]; a1 += hv * w[1]; a2 += hv * w[2]; a3 += hv * w[3];
    }
    red[threadIdx.x * 4 + 0] = a0;
    red[threadIdx.x * 4 + 1] = a1;
    red[threadIdx.x * 4 + 2] = a2;
    red[threadIdx.x * 4 + 3] = a3;
    __syncthreads();
    for (int s = 64; s > 0; s >>= 1) {
        if (threadIdx.x < (unsigned)s) {
            red[threadIdx.x * 4 + 0] += red[(threadIdx.x + s) * 4 + 0];
            red[threadIdx.x * 4 + 1] += red[(threadIdx.x + s) * 4 + 1];
            red[threadIdx.x * 4 + 2] += red[(threadIdx.x + s) * 4 + 2];
            red[threadIdx.x * 4 + 3] += red[(threadIdx.x + s) * 4 + 3];
        }
        __syncthreads();
    }
    if (threadIdx.x == 0) {
        float d0 = red[0] + b3[0];
        float d1 = red[1] + b3[1];
        float d2 = red[2] + b3[2];
        float d3 = red[3] + b3[3];
        float4 b = g_sel[m];
        bool keep = (g_keep[m] != 0);
        float* o = out + m * 5;
        if (keep) {
            float acx = b.x + b.z * 0.5f;
            float acy = b.y + b.w * 0.5f;
            float cx = acx + d0 * b.z;
            float cy = acy + d1 * b.w;
            float w  = b.z * expf(d2);
            float hh = b.w * expf(d3);
            float sc = g_valid[m] ? g_topscore[m] : 0.0f;
            o[0] = cx - w * 0.5f;
            o[1] = cy - hh * 0.5f;
            o[2] = w;
            o[3] = hh;
            o[4] = sc;
        } else {
            o[0] = 0.f; o[1] = 0.f; o[2] = 0.f; o[3] = 0.f; o[4] = 0.f;
        }
    }
}

// ---------------- launch -----------------------------------------------------

extern "C" void kernel_launch(void* const* d_in, const int* in_sizes, int n_in,
                              void* d_out, int out_size) {
    const float* features = (const float*)d_in[0];
    const float* rpn_obj  = (const float*)d_in[1];
    const float* rpn_reg  = (const float*)d_in[2];
    const float* anchors  = (const float*)d_in[3];
    const float* W1 = (const float*)d_in[4];
    const float* b1 = (const float*)d_in[5];
    const float* W2 = (const float*)d_in[6];
    const float* b2 = (const float*)d_in[7];
    const float* W3 = (const float*)d_in[8];
    const float* b3 = (const float*)d_in[9];
    float* out = (float*)d_out;

    float *p_pooled, *p_h1, *p_h2;
    cudaGetSymbolAddress((void**)&p_pooled, g_pooled);
    cudaGetSymbolAddress((void**)&p_h1, g_h1);
    cudaGetSymbolAddress((void**)&p_h2, g_h2);

    k_zero<<<8, 256>>>();
    k_scorebox<<<NA / 256, 256>>>(rpn_obj, rpn_reg, anchors);
    k_cutoff<<<1, 1>>>();
    k_compact<<<NA / 256, 256>>>();
    k_sortselect<<<1, 1024>>>();
    k_adj<<<32, 256>>>();
    k_nms<<<1, 512>>>();
    k_roialign<<<dim3(9, 512), 256>>>(features);
    k_gemm<<<dim3(HIDDEN / 64, MAXDET / 64), 256>>>(p_pooled, W1, b1, p_h1,
                                                    MAXDET, HIDDEN, PD, 1);
    k_gemm<<<dim3(HIDDEN / 64, MAXDET / 64), 256>>>(p_h1, W2, b2, p_h2,
                                                    MAXDET, HIDDEN, HIDDEN, 1);
    k_final<<<MAXDET, 128>>>(W3, b3, out);
}

// round 4
// speedup vs baseline: 1.4304x; 1.4304x over previous
#include <cuda_runtime.h>
#include <math.h>
#include <stdint.h>

#define HFD 128
#define WFD 128
#define DFD 512
#define NA  65536
#define MAXDET 512
#define HIDDEN 1024
#define PD 4608          // 3*3*512
#define NBINS 2048
#define MAXCAND 4096

// ---------------- scratch (device globals; no allocation allowed) ----------
__device__ float    g_scores[NA];
__device__ float4   g_boxes[NA];
__device__ unsigned g_hist[NBINS];
__device__ unsigned g_candCount;
__device__ unsigned g_cutoff;
__device__ unsigned long long g_cand[MAXCAND];
__device__ float    g_topscore[MAXDET];
__device__ int      g_valid[MAXDET];
__device__ float4   g_sel[MAXDET];
__device__ unsigned g_adj[MAXDET * 16];
__device__ unsigned char g_keep[MAXDET];
__device__ __align__(16) float g_pooled[MAXDET * PD];
__device__ __align__(16) float g_h1[MAXDET * HIDDEN];
__device__ __align__(16) float g_h2[MAXDET * HIDDEN];

// ---------------- kernels ---------------------------------------------------

__global__ void k_zero() {
    int t = blockIdx.x * blockDim.x + threadIdx.x;
    if (t < NBINS) g_hist[t] = 0u;
    if (t == 0)    g_candCount = 0u;
}

// scores, boxes, histogram of score bits (scores in (0.5, 1.0])
__global__ void k_scorebox(const float* __restrict__ obj,
                           const float* __restrict__ reg,
                           const float* __restrict__ anchors) {
    __shared__ unsigned sh[NBINS];
    for (int i = threadIdx.x; i < NBINS; i += blockDim.x) sh[i] = 0u;
    __syncthreads();

    int a  = blockIdx.x * blockDim.x + threadIdx.x;   // 0..65535
    int kk = a & 3;
    int jj = (a >> 2) & 127;
    int ii = a >> 9;
    int pix = ii * WFD + jj;

    float o0 = obj[pix * 8 + 2 * kk];
    float o1 = obj[pix * 8 + 2 * kk + 1];
    float mx = fmaxf(o0, o1);
    float e0 = expf(o0 - mx), e1 = expf(o1 - mx);
    float s  = e1 / (e0 + e1);
    g_scores[a] = s;

    const float* r = reg + pix * 16 + 4 * kk;
    float r0 = r[0], r1 = r[1], r2 = r[2], r3 = r[3];
    const float* an = anchors + a * 4;
    float ax = an[0], ay = an[1], aw = an[2], ah = an[3];
    float acx = ax + aw * 0.5f;
    float acy = ay + ah * 0.5f;
    float cx = acx + r0 * aw;
    float cy = acy + r1 * ah;
    float w  = aw * expf(r2);
    float h  = ah * expf(r3);
    g_boxes[a] = make_float4(cx - w * 0.5f, cy - h * 0.5f, w, h);

    if (s > 0.5f) {
        unsigned bits = __float_as_uint(s);
        unsigned bin  = (bits - 0x3F000001u) >> 12;   // 0..2047, monotone
        atomicAdd(&sh[bin], 1u);
    }
    __syncthreads();
    for (int i = threadIdx.x; i < NBINS; i += blockDim.x)
        if (sh[i]) atomicAdd(&g_hist[i], sh[i]);
}

__global__ void k_cutoff() {
    unsigned cum = 0;
    int b;
    for (b = NBINS - 1; b >= 0; b--) {
        cum += g_hist[b];
        if (cum >= MAXDET) break;
    }
    if (b < 0) b = 0;
    g_cutoff = (unsigned)b;
}

__global__ void k_compact() {
    int a = blockIdx.x * blockDim.x + threadIdx.x;
    float s = g_scores[a];
    if (s > 0.5f) {
        unsigned bits = __float_as_uint(s);
        unsigned bin  = (bits - 0x3F000001u) >> 12;
        if (bin >= g_cutoff) {
            unsigned pos = atomicAdd(&g_candCount, 1u);
            if (pos < MAXCAND)
                g_cand[pos] = ((unsigned long long)bits << 32)
                            | (unsigned long long)(0xFFFFFFFFu - (unsigned)a);
        }
    }
}

// bitonic sort candidates descending; emit top-512 (score, idx, sel box, valid)
__global__ void k_sortselect() {
    __shared__ unsigned long long s[MAXCAND];   // 32 KB
    unsigned n = g_candCount;
    if (n > MAXCAND) n = MAXCAND;
    for (int i = threadIdx.x; i < MAXCAND; i += blockDim.x)
        s[i] = (i < (int)n) ? g_cand[i] : 0ull;
    __syncthreads();

    for (int k = 2; k <= MAXCAND; k <<= 1) {
        for (int j = k >> 1; j > 0; j >>= 1) {
            for (int i = threadIdx.x; i < MAXCAND; i += blockDim.x) {
                int ixj = i ^ j;
                if (ixj > i) {
                    unsigned long long va = s[i], vb = s[ixj];
                    bool swp = ((i & k) == 0) ? (va < vb) : (va > vb);
                    if (swp) { s[i] = vb; s[ixj] = va; }
                }
            }
            __syncthreads();
        }
    }

    for (int i = threadIdx.x; i < MAXDET; i += blockDim.x) {
        unsigned long long key = s[i];
        if (key != 0ull) {
            unsigned bits = (unsigned)(key >> 32);
            unsigned idx  = 0xFFFFFFFFu - (unsigned)(key & 0xFFFFFFFFull);
            g_topscore[i] = __uint_as_float(bits);
            g_valid[i]    = 1;
            g_sel[i]      = g_boxes[idx];
        } else {
            g_topscore[i] = 0.0f;
            g_valid[i]    = 0;
            g_sel[i]      = make_float4(0.f, 0.f, 0.f, 0.f);
        }
    }
}

// adjacency bitmask: word w of row i holds bits for j in [32w, 32w+32), j<i, iou>0.3
__global__ void k_adj() {
    int t = blockIdx.x * blockDim.x + threadIdx.x;   // 0..8191
    int i = t >> 4;
    int w = t & 15;
    float4 bi = g_sel[i];
    float x1i = bi.x, y1i = bi.y;
    float x2i = bi.x + bi.z, y2i = bi.y + bi.w;
    float areai = bi.z * bi.w;
    unsigned mask = 0u;
    int j0 = w * 32;
    #pragma unroll 4
    for (int jj = 0; jj < 32; jj++) {
        int j = j0 + jj;
        if (j >= i) break;
        float4 bj = g_sel[j];
        float x2j = bj.x + bj.z, y2j = bj.y + bj.w;
        float ix = fminf(x2i, x2j) - fmaxf(x1i, bj.x);
        ix = fmaxf(0.0f, ix);
        float iy = fminf(y2i, y2j) - fmaxf(y1i, bj.y);
        iy = fmaxf(0.0f, iy);
        float inter = ix * iy;
        float areaj = bj.z * bj.w;
        float iou = inter / (areai + areaj - inter + 1e-8f);
        if (iou > 0.3f) mask |= (1u << jj);
    }
    g_adj[t] = mask;
}

// sequential NMS scan over 512-bit keep mask (warp 0; adjacency in smem)
__global__ void k_nms() {
    __shared__ unsigned s_adj[MAXDET * 16];
    __shared__ int s_valid[MAXDET];
    __shared__ unsigned s_kw[16];
    int t = threadIdx.x;
    for (int i = t; i < MAXDET * 16; i += blockDim.x) s_adj[i] = g_adj[i];
    if (t < MAXDET) s_valid[t] = g_valid[t];
    __syncthreads();

    if (t < 32) {
        unsigned kw = 0u;
        for (int i = 0; i < MAXDET; i++) {
            unsigned w = (t < 16) ? s_adj[i * 16 + t] : 0u;
            bool sup = __any_sync(0xffffffffu, (w & kw) != 0u);
            bool k = (s_valid[i] != 0) && !sup;
            if (t == (i >> 5)) kw |= ((unsigned)k) << (i & 31);
        }
        if (t < 16) s_kw[t] = kw;
    }
    __syncthreads();
    if (t < MAXDET) g_keep[t] = (unsigned char)((s_kw[t >> 5] >> (t & 31)) & 1u);
}

// ROIAlign: block = (tile 0..8, box 0..511); threads over channels
__global__ void k_roialign(const float* __restrict__ feat) {
    int tile = blockIdx.x;
    int m    = blockIdx.y;
    int ty = tile / 3, tx = tile % 3;
    float4 b = g_sel[m];

    int x0[2], x1[2], y0[2], y1[2];
    float wx[2], wy[2];
    #pragma unroll
    for (int p = 0; p < 2; p++) {
        {
            int sx = tx * 2 + p;
            float tt = ((float)sx + 0.5f) / 6.0f;
            float c = (b.x + tt * b.z) / 16.0f - 0.5f;
            c = fminf(fmaxf(c, 0.0f), 127.0f);
            int c0 = (int)floorf(c);
            x0[p] = c0;
            x1[p] = min(c0 + 1, 127);
            wx[p] = c - (float)c0;
        }
        {
            int sy = ty * 2 + p;
            float tt = ((float)sy + 0.5f) / 6.0f;
            float c = (b.y + tt * b.w) / 16.0f - 0.5f;
            c = fminf(fmaxf(c, 0.0f), 127.0f);
            int c0 = (int)floorf(c);
            y0[p] = c0;
            y1[p] = min(c0 + 1, 127);
            wy[p] = c - (float)c0;
        }
    }

    for (int c = threadIdx.x; c < DFD; c += blockDim.x) {
        float mv = -INFINITY;
        #pragma unroll
        for (int py = 0; py < 2; py++) {
            float w0y = 1.0f - wy[py], w1y = wy[py];
            #pragma unroll
            for (int px = 0; px < 2; px++) {
                float w0x = 1.0f - wx[px], w1x = wx[px];
                float f00 = feat[(y0[py] * WFD + x0[px]) * DFD + c];
                float f01 = feat[(y0[py] * WFD + x1[px]) * DFD + c];
                float f10 = feat[(y1[py] * WFD + x0[px]) * DFD + c];
                float f11 = feat[(y1[py] * WFD + x1[px]) * DFD + c];
                float v = ((f00 * w0y) * w0x) + ((f01 * w0y) * w1x)
                        + ((f10 * w1y) * w0x) + ((f11 * w1y) * w1x);
                mv = fmaxf(mv, v);
            }
        }
        g_pooled[(m * 9 + tile) * DFD + c] = mv;
    }
}

// ---------------- tf32x3 tensor-core GEMM -----------------------------------
// C[MxN] = relu?(A[MxK] @ B[KxN] + bias), tiles 64x64x32, 4 warps, cp.async x2
#define GBM 64
#define GBN 64
#define GBK 32
#define SA_STRIDE 36
#define SB_STRIDE 72

__device__ __forceinline__ float tf32_rna(float x) {
    float r;
    asm("cvt.rna.tf32.f32 %0, %1;" : "=f"(r) : "f"(x));
    return r;
}

__device__ __forceinline__ void mma_tf32(float* d, const unsigned* a, const unsigned* b) {
    asm volatile(
        "mma.sync.aligned.m16n8k8.row.col.f32.tf32.tf32.f32 "
        "{%0,%1,%2,%3}, {%4,%5,%6,%7}, {%8,%9}, {%0,%1,%2,%3};"
        : "+f"(d[0]), "+f"(d[1]), "+f"(d[2]), "+f"(d[3])
        : "r"(a[0]), "r"(a[1]), "r"(a[2]), "r"(a[3]), "r"(b[0]), "r"(b[1]));
}

__global__ __launch_bounds__(128) void k_gemm_tc(const float* __restrict__ A,
                                                 const float* __restrict__ B,
                                                 const float* __restrict__ bias,
                                                 float* __restrict__ C,
                                                 int M, int N, int K, int relu) {
    __shared__ float sA[2][GBM * SA_STRIDE];   // [row][k], padded
    __shared__ float sB[2][GBK * SB_STRIDE];   // [k][col], padded

    int tid = threadIdx.x;
    int rowBase = blockIdx.y * GBM;
    int colBase = blockIdx.x * GBN;
    int w = tid >> 5;
    int lane = tid & 31;
    int warpM = w >> 1, warpN = w & 1;
    int lr = lane >> 2, lc = lane & 3;

    // per-stage load indices
    int arow = tid >> 3;           // 0..15 (i*16 added)
    int acol = (tid & 7) << 2;     // 0,4,..28
    int brow = tid >> 4;           // 0..7 (i*8 added)
    int bcol = (tid & 15) << 2;    // 0..60

    float acc[2][4][4];
    #pragma unroll
    for (int mt = 0; mt < 2; mt++)
        #pragma unroll
        for (int nt = 0; nt < 4; nt++)
            #pragma unroll
            for (int q = 0; q < 4; q++) acc[mt][nt][q] = 0.0f;

    int niter = K / GBK;

    // prologue: load stage 0
    {
        const float* Ab = A + (size_t)rowBase * K;
        const float* Bb = B + colBase;
        #pragma unroll
        for (int i = 0; i < 4; i++) {
            int r = i * 16 + arow;
            unsigned dst = (unsigned)__cvta_generic_to_shared(&sA[0][r * SA_STRIDE + acol]);
            const float* src = Ab + (size_t)r * K + acol;
            asm volatile("cp.async.cg.shared.global [%0], [%1], 16;\n" :: "r"(dst), "l"(src));
        }
        #pragma unroll
        for (int i = 0; i < 4; i++) {
            int kr = i * 8 + brow;
            unsigned dst = (unsigned)__cvta_generic_to_shared(&sB[0][kr * SB_STRIDE + bcol]);
            const float* src = Bb + (size_t)kr * N + bcol;
            asm volatile("cp.async.cg.shared.global [%0], [%1], 16;\n" :: "r"(dst), "l"(src));
        }
        asm volatile("cp.async.commit_group;\n");
    }

    for (int it = 0; it < niter; it++) {
        // prefetch next stage
        if (it + 1 < niter) {
            int k0 = (it + 1) * GBK;
            int st = (it + 1) & 1;
            const float* Ab = A + (size_t)rowBase * K + k0;
            const float* Bb = B + (size_t)k0 * N + colBase;
            #pragma unroll
            for (int i = 0; i < 4; i++) {
                int r = i * 16 + arow;
                unsigned dst = (unsigned)__cvta_generic_to_shared(&sA[st][r * SA_STRIDE + acol]);
                const float* src = Ab + (size_t)r * K + acol;
                asm volatile("cp.async.cg.shared.global [%0], [%1], 16;\n" :: "r"(dst), "l"(src));
            }
            #pragma unroll
            for (int i = 0; i < 4; i++) {
                int kr = i * 8 + brow;
                unsigned dst = (unsigned)__cvta_generic_to_shared(&sB[st][kr * SB_STRIDE + bcol]);
                const float* src = Bb + (size_t)kr * N + bcol;
                asm volatile("cp.async.cg.shared.global [%0], [%1], 16;\n" :: "r"(dst), "l"(src));
            }
        }
        asm volatile("cp.async.commit_group;\n");
        asm volatile("cp.async.wait_group 1;\n");
        __syncthreads();

        int st = it & 1;
        const float* cA = sA[st];
        const float* cB = sB[st];

        #pragma unroll
        for (int ks = 0; ks < 4; ks++) {
            int k = ks * 8;
            unsigned ahi[2][4], alo[2][4];
            #pragma unroll
            for (int mt = 0; mt < 2; mt++) {
                int r0 = warpM * 32 + mt * 16 + lr;
                float av[4];
                av[0] = cA[r0 * SA_STRIDE + k + lc];
                av[1] = cA[(r0 + 8) * SA_STRIDE + k + lc];
                av[2] = cA[r0 * SA_STRIDE + k + 4 + lc];
                av[3] = cA[(r0 + 8) * SA_STRIDE + k + 4 + lc];
                #pragma unroll
                for (int q = 0; q < 4; q++) {
                    float hi = tf32_rna(av[q]);
                    float lo = tf32_rna(av[q] - hi);
                    ahi[mt][q] = __float_as_uint(hi);
                    alo[mt][q] = __float_as_uint(lo);
                }
            }
            unsigned bhi[4][2], blo[4][2];
            #pragma unroll
            for (int nt = 0; nt < 4; nt++) {
                int col = warpN * 32 + nt * 8 + lr;
                float bv[2];
                bv[0] = cB[(k + lc) * SB_STRIDE + col];
                bv[1] = cB[(k + 4 + lc) * SB_STRIDE + col];
                #pragma unroll
                for (int q = 0; q < 2; q++) {
                    float hi = tf32_rna(bv[q]);
                    float lo = tf32_rna(bv[q] - hi);
                    bhi[nt][q] = __float_as_uint(hi);
                    blo[nt][q] = __float_as_uint(lo);
                }
            }
            #pragma unroll
            for (int mt = 0; mt < 2; mt++)
                #pragma unroll
                for (int nt = 0; nt < 4; nt++) {
                    mma_tf32(acc[mt][nt], ahi[mt], bhi[nt]);
                    mma_tf32(acc[mt][nt], ahi[mt], blo[nt]);
                    mma_tf32(acc[mt][nt], alo[mt], bhi[nt]);
                }
        }
        __syncthreads();
    }

    // epilogue
    #pragma unroll
    for (int nt = 0; nt < 4; nt++) {
        int col = colBase + warpN * 32 + nt * 8 + lc * 2;
        float2 bb = *(const float2*)(bias + col);
        #pragma unroll
        for (int mt = 0; mt < 2; mt++) {
            int row0 = rowBase + warpM * 32 + mt * 16 + lr;
            float2 v0 = make_float2(acc[mt][nt][0] + bb.x, acc[mt][nt][1] + bb.y);
            float2 v1 = make_float2(acc[mt][nt][2] + bb.x, acc[mt][nt][3] + bb.y);
            if (relu) {
                v0.x = fmaxf(v0.x, 0.f); v0.y = fmaxf(v0.y, 0.f);
                v1.x = fmaxf(v1.x, 0.f); v1.y = fmaxf(v1.y, 0.f);
            }
            *(float2*)(C + (size_t)row0 * N + col) = v0;
            *(float2*)(C + (size_t)(row0 + 8) * N + col) = v1;
        }
    }
}

// GEMM3 (512x4x1024) + unparameterize + keep/valid epilogue
__global__ void k_final(const float* __restrict__ W3,
                        const float* __restrict__ b3,
                        float* __restrict__ out) {
    int m = blockIdx.x;
    __shared__ float red[128 * 4];
    float a0 = 0.f, a1 = 0.f, a2 = 0.f, a3 = 0.f;
    const float* h = g_h2 + m * HIDDEN;
    for (int k = threadIdx.x; k < HIDDEN; k += 128) {
        float hv = h[k];
        const float* w = W3 + k * 4;
        a0 += hv * w[0]; a1 += hv * w[1]; a2 += hv * w[2]; a3 += hv * w[3];
    }
    red[threadIdx.x * 4 + 0] = a0;
    red[threadIdx.x * 4 + 1] = a1;
    red[threadIdx.x * 4 + 2] = a2;
    red[threadIdx.x * 4 + 3] = a3;
    __syncthreads();
    for (int s = 64; s > 0; s >>= 1) {
        if (threadIdx.x < (unsigned)s) {
            red[threadIdx.x * 4 + 0] += red[(threadIdx.x + s) * 4 + 0];
            red[threadIdx.x * 4 + 1] += red[(threadIdx.x + s) * 4 + 1];
            red[threadIdx.x * 4 + 2] += red[(threadIdx.x + s) * 4 + 2];
            red[threadIdx.x * 4 + 3] += red[(threadIdx.x + s) * 4 + 3];
        }
        __syncthreads();
    }
    if (threadIdx.x == 0) {
        float d0 = red[0] + b3[0];
        float d1 = red[1] + b3[1];
        float d2 = red[2] + b3[2];
        float d3 = red[3] + b3[3];
        float4 b = g_sel[m];
        bool keep = (g_keep[m] != 0);
        float* o = out + m * 5;
        if (keep) {
            float acx = b.x + b.z * 0.5f;
            float acy = b.y + b.w * 0.5f;
            float cx = acx + d0 * b.z;
            float cy = acy + d1 * b.w;
            float w  = b.z * expf(d2);
            float hh = b.w * expf(d3);
            float sc = g_valid[m] ? g_topscore[m] : 0.0f;
            o[0] = cx - w * 0.5f;
            o[1] = cy - hh * 0.5f;
            o[2] = w;
            o[3] = hh;
            o[4] = sc;
        } else {
            o[0] = 0.f; o[1] = 0.f; o[2] = 0.f; o[3] = 0.f; o[4] = 0.f;
        }
    }
}

// ---------------- launch -----------------------------------------------------

extern "C" void kernel_launch(void* const* d_in, const int* in_sizes, int n_in,
                              void* d_out, int out_size) {
    const float* features = (const float*)d_in[0];
    const float* rpn_obj  = (const float*)d_in[1];
    const float* rpn_reg  = (const float*)d_in[2];
    const float* anchors  = (const float*)d_in[3];
    const float* W1 = (const float*)d_in[4];
    const float* b1 = (const float*)d_in[5];
    const float* W2 = (const float*)d_in[6];
    const float* b2 = (const float*)d_in[7];
    const float* W3 = (const float*)d_in[8];
    const float* b3 = (const float*)d_in[9];
    float* out = (float*)d_out;

    float *p_pooled, *p_h1, *p_h2;
    cudaGetSymbolAddress((void**)&p_pooled, g_pooled);
    cudaGetSymbolAddress((void**)&p_h1, g_h1);
    cudaGetSymbolAddress((void**)&p_h2, g_h2);

    k_zero<<<8, 256>>>();
    k_scorebox<<<NA / 256, 256>>>(rpn_obj, rpn_reg, anchors);
    k_cutoff<<<1, 1>>>();
    k_compact<<<NA / 256, 256>>>();
    k_sortselect<<<1, 1024>>>();
    k_adj<<<32, 256>>>();
    k_nms<<<1, 512>>>();
    k_roialign<<<dim3(9, 512), 256>>>(features);
    k_gemm_tc<<<dim3(HIDDEN / GBN, MAXDET / GBM), 128>>>(p_pooled, W1, b1, p_h1,
                                                         MAXDET, HIDDEN, PD, 1);
    k_gemm_tc<<<dim3(HIDDEN / GBN, MAXDET / GBM), 128>>>(p_h1, W2, b2, p_h2,
                                                         MAXDET, HIDDEN, HIDDEN, 1);
    k_final<<<MAXDET, 128>>>(W3, b3, out);
}